// round 6
// baseline (speedup 1.0000x reference)
#include <cuda_runtime.h>
#include <cuda_bf16.h>
#include <math.h>
#include <stdint.h>

namespace {
constexpr int B_ = 256;
constexpr int S_ = 128;
constexpr int H_ = 512;
constexpr int E_ = 512;
constexpr int V_ = 32000;
constexpr int IN_ = E_ + 2 * H_;   // 1536
constexpr int G_ = 3 * H_;         // 1536
}

// ---------------- static scratch ----------------
__device__ float g_x[B_ * IN_];
__device__ float g_gi[B_ * G_];
__device__ float g_gh[B_ * G_];
__device__ float g_hidden[B_ * H_];
__device__ float g_sc[B_ * S_];
__device__ float g_attn[B_ * S_];

// ---------------- helpers ----------------
__device__ __forceinline__ void cp_async16(uint32_t s, const void* g) {
    asm volatile("cp.async.cg.shared.global [%0], [%1], 16;\n"
                 :: "r"(s), "l"(g) : "memory");
}
__device__ __forceinline__ void cp_commit() {
    asm volatile("cp.async.commit_group;\n" ::: "memory");
}
template <int N>
__device__ __forceinline__ void cp_wait() {
    asm volatile("cp.async.wait_group %0;\n" :: "n"(N) : "memory");
}
__device__ __forceinline__ uint32_t smem_u32(const void* p) {
    uint32_t a;
    asm("{ .reg .u64 t; cvta.to.shared.u64 t, %1; cvt.u32.u64 %0, t; }"
        : "=r"(a) : "l"(p));
    return a;
}
__device__ __forceinline__ void mma16816(float* d, const uint32_t* a,
                                         const uint32_t* b) {
    asm volatile(
        "mma.sync.aligned.m16n8k16.row.col.f32.bf16.bf16.f32 "
        "{%0,%1,%2,%3}, {%4,%5,%6,%7}, {%8,%9}, {%0,%1,%2,%3};\n"
        : "+f"(d[0]), "+f"(d[1]), "+f"(d[2]), "+f"(d[3])
        : "r"(a[0]), "r"(a[1]), "r"(a[2]), "r"(a[3]), "r"(b[0]), "r"(b[1]));
}
// pack 2 fp32 -> bf16x2 (f.x in low half)
__device__ __forceinline__ uint32_t f2bf2(float2 f) {
    uint32_t r;
    asm("cvt.rn.bf16x2.f32 %0, %1, %2;" : "=r"(r) : "f"(f.y), "f"(f.x));
    return r;
}
// unpack bf16x2 -> 2 fp32 (exact)
__device__ __forceinline__ float2 bf2f2(uint32_t h) {
    float lo = __uint_as_float(h << 16);
    float hi = __uint_as_float(h & 0xffff0000u);
    return make_float2(lo, hi);
}
// hi/lo split of a float2 into two bf16x2 regs
__device__ __forceinline__ void split2(float2 f, uint32_t& hi, uint32_t& lo) {
    hi = f2bf2(f);
    float2 fh = bf2f2(hi);
    lo = f2bf2(make_float2(f.x - fh.x, f.y - fh.y));
}

// ---------------- elementwise kernels ----------------
__global__ void build_x_kernel(const int* __restrict__ ids,
                               const float* __restrict__ emb,
                               const float* __restrict__ weighted) {
    int idx = blockIdx.x * blockDim.x + threadIdx.x;  // < B*IN
    int b = idx / IN_;
    int j = idx - b * IN_;
    g_x[idx] = (j < E_) ? emb[(size_t)ids[b] * E_ + j]
                        : weighted[b * (2 * H_) + (j - E_)];
}

__global__ void zero_sc_kernel() {
    int idx = blockIdx.x * blockDim.x + threadIdx.x;
    g_sc[idx] = 0.f;
}

// ---------------- fused split + mma.sync GEMM (register convert) ----------
// C[M,N] = A[M,K] @ W[N,K]^T, fp32-equivalent via 3-term bf16 split.
// fp32 tiles cp.async'd into swizzled staging; MMA fragments are LDS.64'd
// directly from staging and converted to bf16 hi/lo in registers (no bf16
// SMEM tiles, no ldmatrix). One fp32 load serves all three split passes.
// MODE 0: C[m,n] = acc + bias[n]
// MODE 1: sc[m] += sum_n tanh(acc + bias[n]) * hidden[m>>7, n]
constexpr int GM = 128, GN = 128;
constexpr int STG = 128 * 128;            // 16384 B per fp32 tile (128 rows x 128B)
constexpr int STG_STAGE = 2 * STG;        // A + B per stage
constexpr int STAGES = 3;
constexpr int MMA_SMEM = STAGES * STG_STAGE;  // 98304 B

__device__ __forceinline__ uint32_t stg_sw(int row, int byteInRow) {
    uint32_t off = (uint32_t)(row * 128 + byteInRow);
    return off ^ ((uint32_t)(row & 7) << 4);
}

template <int MODE>
__global__ void __launch_bounds__(256, 2)
mma_gemm(const float* __restrict__ Af, const float* __restrict__ Bf,
         const float* __restrict__ bias, float* __restrict__ C,
         int M, int N, int K,
         const float* __restrict__ hidden, float* __restrict__ scOut) {
    extern __shared__ __align__(16) char smem[];
    const int t = threadIdx.x;
    const int lane = t & 31;
    const int wid = t >> 5;
    const int wm = wid & 1;      // 64-row slab
    const int wn = wid >> 1;     // 32-col slab
    const int m0 = blockIdx.y * GM, n0 = blockIdx.x * GN;
    const uint32_t sb = smem_u32(smem);

    float acc[4][4][4];
#pragma unroll
    for (int i = 0; i < 4; i++)
#pragma unroll
        for (int j = 0; j < 4; j++)
#pragma unroll
            for (int r = 0; r < 4; r++) acc[i][j][r] = 0.f;

    const int KT = K / 32;
    const int cr = t >> 2;              // load row 0..63 (+64)
    const int cq = t & 3;               // 32B column quad

    auto issue_load = [&](int it) {
        const int kk = it * 32;
        uint32_t stA = sb + (uint32_t)(it % STAGES) * STG_STAGE;
        uint32_t stB = stA + STG;
        const float* Ap = Af + (size_t)(m0 + cr) * K + kk + cq * 8;
        const float* Bp = Bf + (size_t)(n0 + cr) * K + kk + cq * 8;
#pragma unroll
        for (int h = 0; h < 2; h++) {   // rows cr, cr+64
            int row = cr + h * 64;
            cp_async16(stA + stg_sw(row, cq * 32),      Ap + (size_t)h * 64 * K);
            cp_async16(stA + stg_sw(row, cq * 32 + 16), Ap + (size_t)h * 64 * K + 4);
            cp_async16(stB + stg_sw(row, cq * 32),      Bp + (size_t)h * 64 * K);
            cp_async16(stB + stg_sw(row, cq * 32 + 16), Bp + (size_t)h * 64 * K + 4);
        }
        cp_commit();
    };

    const int g = lane >> 2, q = lane & 3;

    issue_load(0);
    if (KT > 1) issue_load(1);

    for (int it = 0; it < KT; ++it) {
        if (it + 1 < KT) cp_wait<1>(); else cp_wait<0>();
        __syncthreads();   // staging ready; prior-iter reads finished everywhere
        if (it + 2 < KT) issue_load(it + 2);

        const uint32_t aOff = (uint32_t)(it % STAGES) * STG_STAGE;
        const uint32_t bOff = aOff + STG;

#pragma unroll
        for (int ks = 0; ks < 2; ks++) {
            const int kb = ks * 64;   // byte offset of this k16 within chunk
            // B fragments for the warp's 32 columns: hi + lo
            uint32_t bh[4][2], bl[4][2];
#pragma unroll
            for (int nj = 0; nj < 4; nj++) {
                int row = wn * 32 + nj * 8 + g;
#pragma unroll
                for (int h = 0; h < 2; h++) {
                    float2 f = *reinterpret_cast<const float2*>(
                        smem + bOff + stg_sw(row, kb + h * 32 + q * 8));
                    split2(f, bh[nj][h], bl[nj][h]);
                }
            }
            // A fragments per mi, reused across all 3 passes
#pragma unroll
            for (int mi = 0; mi < 4; mi++) {
                int r0 = wm * 64 + mi * 16 + g;
                int r1 = r0 + 8;
                float2 f0 = *reinterpret_cast<const float2*>(
                    smem + aOff + stg_sw(r0, kb + q * 8));
                float2 f1 = *reinterpret_cast<const float2*>(
                    smem + aOff + stg_sw(r1, kb + q * 8));
                float2 f2 = *reinterpret_cast<const float2*>(
                    smem + aOff + stg_sw(r0, kb + 32 + q * 8));
                float2 f3 = *reinterpret_cast<const float2*>(
                    smem + aOff + stg_sw(r1, kb + 32 + q * 8));
                uint32_t ah[4], al[4];
                split2(f0, ah[0], al[0]);
                split2(f1, ah[1], al[1]);
                split2(f2, ah[2], al[2]);
                split2(f3, ah[3], al[3]);
#pragma unroll
                for (int nj = 0; nj < 4; nj++) mma16816(acc[mi][nj], ah, bh[nj]);
#pragma unroll
                for (int nj = 0; nj < 4; nj++) mma16816(acc[mi][nj], al, bh[nj]);
#pragma unroll
                for (int nj = 0; nj < 4; nj++) mma16816(acc[mi][nj], ah, bl[nj]);
            }
        }
    }

    // ---------------- epilogue ----------------
    if (MODE == 0) {
#pragma unroll
        for (int mi = 0; mi < 4; mi++) {
            int row0 = m0 + wm * 64 + mi * 16 + g;
            int row1 = row0 + 8;
#pragma unroll
            for (int nj = 0; nj < 4; nj++) {
                int col = n0 + wn * 32 + nj * 8 + 2 * q;
                float b0 = bias[col], b1 = bias[col + 1];
                float2 o0 = make_float2(acc[mi][nj][0] + b0, acc[mi][nj][1] + b1);
                float2 o1 = make_float2(acc[mi][nj][2] + b0, acc[mi][nj][3] + b1);
                *reinterpret_cast<float2*>(&C[(size_t)row0 * N + col]) = o0;
                *reinterpret_cast<float2*>(&C[(size_t)row1 * N + col]) = o1;
            }
        }
    } else {
        const int b = m0 >> 7;   // GM == S_
#pragma unroll
        for (int mi = 0; mi < 4; mi++) {
            float p0 = 0.f, p1 = 0.f;
#pragma unroll
            for (int nj = 0; nj < 4; nj++) {
                int col = n0 + wn * 32 + nj * 8 + 2 * q;
                float bz0 = bias[col], bz1 = bias[col + 1];
                float hv0 = hidden[b * H_ + col], hv1 = hidden[b * H_ + col + 1];
                p0 = fmaf(tanhf(acc[mi][nj][0] + bz0), hv0, p0);
                p0 = fmaf(tanhf(acc[mi][nj][1] + bz1), hv1, p0);
                p1 = fmaf(tanhf(acc[mi][nj][2] + bz0), hv0, p1);
                p1 = fmaf(tanhf(acc[mi][nj][3] + bz1), hv1, p1);
            }
            p0 += __shfl_xor_sync(0xffffffffu, p0, 1);
            p0 += __shfl_xor_sync(0xffffffffu, p0, 2);
            p1 += __shfl_xor_sync(0xffffffffu, p1, 1);
            p1 += __shfl_xor_sync(0xffffffffu, p1, 2);
            if (q == 0) {
                int row = m0 + wm * 64 + mi * 16 + g;
                atomicAdd(&scOut[row], p0);
                atomicAdd(&scOut[row + 8], p1);
            }
        }
    }
}

// ---------------- GRU ----------------
__global__ void gru_kernel(const float* __restrict__ prev,
                           float* __restrict__ outHidden) {
    int idx = blockIdx.x * blockDim.x + threadIdx.x;
    int b = idx >> 9, h = idx & (H_ - 1);
    const float* gi = g_gi + (size_t)b * G_;
    const float* gh = g_gh + (size_t)b * G_;
    float ir = gi[h], iz = gi[h + H_], inn = gi[h + 2 * H_];
    float hr = gh[h], hz = gh[h + H_], hn = gh[h + 2 * H_];
    float r = 1.f / (1.f + expf(-(ir + hr)));
    float z = 1.f / (1.f + expf(-(iz + hz)));
    float n = tanhf(inn + r * hn);
    float hv = (1.f - z) * n + z * prev[idx];
    g_hidden[idx] = hv;
    outHidden[idx] = hv;
}

// ---------------- softmax (online max+sum) ----------------
__global__ void __launch_bounds__(512)
softmax_kernel(float* __restrict__ pred, const int* __restrict__ src,
               const int* __restrict__ ids) {
    __shared__ float s_lc[S_];
    __shared__ float s_m[512];
    __shared__ float s_s[512];
    __shared__ int s_cnt;
    const int b = blockIdx.x, t = threadIdx.x;
    float* row = pred + (size_t)b * V_;

    if (t == 0) s_cnt = 0;
    if (t < S_) {
        float mask = (src[b * S_ + t] == 0) ? -1000.f : 0.f;
        s_lc[t] = tanhf(g_sc[b * S_ + t] + mask);
    }
    __syncthreads();

    float m = -1e30f, s = 0.f;
    for (int v = t; v < V_; v += 512) {
        float x = row[v];
        float nm = fmaxf(m, x);
        s = s * __expf(m - nm) + __expf(x - nm);
        m = nm;
    }
    if (t < S_) {
        float x = s_lc[t];
        float nm = fmaxf(m, x);
        s = s * __expf(m - nm) + __expf(x - nm);
        m = nm;
    }
    s_m[t] = m; s_s[t] = s;
    __syncthreads();
    for (int o = 256; o; o >>= 1) {
        if (t < o) {
            float m1 = s_m[t], m2 = s_m[t + o];
            float nm = fmaxf(m1, m2);
            s_s[t] = s_s[t] * __expf(m1 - nm) + s_s[t + o] * __expf(m2 - nm);
            s_m[t] = nm;
        }
        __syncthreads();
    }
    float gmax = s_m[0];
    float inv = 1.f / s_s[0];

    for (int v = t; v < V_; v += 512) row[v] = __expf(row[v] - gmax) * inv;

    int id = ids[b];
    if (t < S_ && src[b * S_ + t] == id) atomicAdd(&s_cnt, 1);
    __syncthreads();

    if (t < S_) {
        float pc = __expf(s_lc[t] - gmax) * inv;
        atomicAdd(&row[src[b * S_ + t]], pc);
        float eq = (src[b * S_ + t] == id) ? 1.f : 0.f;
        g_attn[b * S_ + t] = pc * eq / fmaxf((float)s_cnt, 1.f);
    }
}

__global__ void __launch_bounds__(256)
weighted_kernel(const float* __restrict__ enc, float* __restrict__ outW) {
    __shared__ float s_a[S_];
    const int b = blockIdx.x, t = threadIdx.x;
    if (t < S_) s_a[t] = g_attn[b * S_ + t];
    __syncthreads();
    float4 acc = make_float4(0.f, 0.f, 0.f, 0.f);
    const float4* e4 = reinterpret_cast<const float4*>(enc + (size_t)b * S_ * (2 * H_));
    for (int s = 0; s < S_; s++) {
        float w = s_a[s];
        if (w != 0.f) {
            float4 e = e4[s * 256 + t];
            acc.x = fmaf(w, e.x, acc.x); acc.y = fmaf(w, e.y, acc.y);
            acc.z = fmaf(w, e.z, acc.z); acc.w = fmaf(w, e.w, acc.w);
        }
    }
    reinterpret_cast<float4*>(outW)[b * 256 + t] = acc;
}

// ---------------- launch ----------------
extern "C" void kernel_launch(void* const* d_in, const int* in_sizes, int n_in,
                              void* d_out, int out_size) {
    const int*   input_ids = (const int*)d_in[0];
    const float* encoded   = (const float*)d_in[1];
    const int*   src       = (const int*)d_in[2];
    const float* prev      = (const float*)d_in[3];
    const float* weighted  = (const float*)d_in[4];
    const float* embed_w   = (const float*)d_in[6];
    const float* w_ih      = (const float*)d_in[7];
    const float* w_hh      = (const float*)d_in[8];
    const float* b_ih      = (const float*)d_in[9];
    const float* b_hh      = (const float*)d_in[10];
    const float* Wo_w      = (const float*)d_in[13];
    const float* Wo_b      = (const float*)d_in[14];
    const float* Wc_w      = (const float*)d_in[15];
    const float* Wc_b      = (const float*)d_in[16];

    float* pred        = (float*)d_out;
    float* outHidden   = pred + (size_t)B_ * V_;
    float* outWeighted = outHidden + (size_t)B_ * H_;

    float *px, *pgi, *pgh, *phid, *psc;
    cudaGetSymbolAddress((void**)&px,   g_x);
    cudaGetSymbolAddress((void**)&pgi,  g_gi);
    cudaGetSymbolAddress((void**)&pgh,  g_gh);
    cudaGetSymbolAddress((void**)&phid, g_hidden);
    cudaGetSymbolAddress((void**)&psc,  g_sc);

    cudaFuncSetAttribute(mma_gemm<0>, cudaFuncAttributeMaxDynamicSharedMemorySize, MMA_SMEM);
    cudaFuncSetAttribute(mma_gemm<1>, cudaFuncAttributeMaxDynamicSharedMemorySize, MMA_SMEM);

    // x = concat(embed[ids], weighted)
    build_x_kernel<<<(B_ * IN_) / 256, 256>>>(input_ids, embed_w, weighted);

    // gi = x @ W_ih^T + b_ih ; gh = prev @ W_hh^T + b_hh
    mma_gemm<0><<<dim3(G_ / GN, B_ / GM), 256, MMA_SMEM>>>(
        px, w_ih, b_ih, pgi, B_, G_, IN_, nullptr, nullptr);
    mma_gemm<0><<<dim3(G_ / GN, B_ / GM), 256, MMA_SMEM>>>(
        prev, w_hh, b_hh, pgh, B_, G_, H_, nullptr, nullptr);

    gru_kernel<<<(B_ * H_) / 256, 256>>>(prev, outHidden);

    // score_g = hidden @ Wo^T + Wo_b
    mma_gemm<0><<<dim3(V_ / GN, B_ / GM), 256, MMA_SMEM>>>(
        phid, Wo_w, Wo_b, pred, B_, V_, H_, nullptr, nullptr);

    // sc = einsum(tanh(enc @ Wc^T + Wc_b), hidden)
    zero_sc_kernel<<<(B_ * S_) / 256, 256>>>();
    mma_gemm<1><<<dim3(H_ / GN, (B_ * S_) / GM), 256, MMA_SMEM>>>(
        encoded, Wc_w, Wc_b, nullptr, B_ * S_, H_, 2 * H_, phid, psc);

    softmax_kernel<<<B_, 512>>>(pred, src, input_ids);
    weighted_kernel<<<B_, 256>>>(encoded, outWeighted);

    (void)in_sizes; (void)n_in; (void)out_size;
}

// round 7
// speedup vs baseline: 1.4197x; 1.4197x over previous
#include <cuda_runtime.h>
#include <cuda_fp16.h>
#include <math.h>
#include <stdint.h>

namespace {
constexpr int B_ = 256;
constexpr int S_ = 128;
constexpr int H_ = 512;
constexpr int E_ = 512;
constexpr int V_ = 32000;
constexpr int IN_ = E_ + 2 * H_;   // 1536
constexpr int G_ = 3 * H_;         // 1536
}

// ---------------- static scratch ----------------
__device__ float g_x[B_ * IN_];
__device__ float g_gi[B_ * G_];
__device__ float g_gh[B_ * G_];
__device__ float g_hidden[B_ * H_];
__device__ float g_sc[B_ * S_];
__device__ float g_attn[B_ * S_];

// ---------------- helpers ----------------
__device__ __forceinline__ void cp_async16(uint32_t s, const void* g) {
    asm volatile("cp.async.cg.shared.global [%0], [%1], 16;\n"
                 :: "r"(s), "l"(g) : "memory");
}
__device__ __forceinline__ void cp_commit() {
    asm volatile("cp.async.commit_group;\n" ::: "memory");
}
template <int N>
__device__ __forceinline__ void cp_wait() {
    asm volatile("cp.async.wait_group %0;\n" :: "n"(N) : "memory");
}
__device__ __forceinline__ uint32_t smem_u32(const void* p) {
    uint32_t a;
    asm("{ .reg .u64 t; cvta.to.shared.u64 t, %1; cvt.u32.u64 %0, t; }"
        : "=r"(a) : "l"(p));
    return a;
}
__device__ __forceinline__ void ldmx4(uint32_t& r0, uint32_t& r1, uint32_t& r2,
                                      uint32_t& r3, uint32_t addr) {
    asm volatile("ldmatrix.sync.aligned.m8n8.x4.shared.b16 {%0,%1,%2,%3}, [%4];\n"
                 : "=r"(r0), "=r"(r1), "=r"(r2), "=r"(r3) : "r"(addr));
}
__device__ __forceinline__ void mma16816(float* d, const uint32_t* a,
                                         const uint32_t* b) {
    asm volatile(
        "mma.sync.aligned.m16n8k16.row.col.f32.f16.f16.f32 "
        "{%0,%1,%2,%3}, {%4,%5,%6,%7}, {%8,%9}, {%0,%1,%2,%3};\n"
        : "+f"(d[0]), "+f"(d[1]), "+f"(d[2]), "+f"(d[3])
        : "r"(a[0]), "r"(a[1]), "r"(a[2]), "r"(a[3]), "r"(b[0]), "r"(b[1]));
}
// fp32x2 -> fp16x2 (f.x low)
__device__ __forceinline__ uint32_t f2h2(float2 f) {
    __half2 h = __float22half2_rn(f);
    return *reinterpret_cast<uint32_t*>(&h);
}
// fp16x2 hi + residual lo
__device__ __forceinline__ void split2h(float2 f, uint32_t& hi, uint32_t& lo) {
    hi = f2h2(f);
    __half2 hh = *reinterpret_cast<__half2*>(&hi);
    float2 fh = __half22float2(hh);
    lo = f2h2(make_float2(f.x - fh.x, f.y - fh.y));
}

// ---------------- elementwise kernels ----------------
__global__ void build_x_kernel(const int* __restrict__ ids,
                               const float* __restrict__ emb,
                               const float* __restrict__ weighted) {
    int idx = blockIdx.x * blockDim.x + threadIdx.x;  // < B*IN
    int b = idx / IN_;
    int j = idx - b * IN_;
    g_x[idx] = (j < E_) ? emb[(size_t)ids[b] * E_ + j]
                        : weighted[b * (2 * H_) + (j - E_)];
}

__global__ void zero_sc_kernel() {
    int idx = blockIdx.x * blockDim.x + threadIdx.x;
    g_sc[idx] = 0.f;
}

// ---------------- fused split + mma.sync fp16 GEMM ----------------
// C[M,N] = A[M,K] @ W[N,K]^T.
// PASSES=2: acc = ah*bh + al*bh        (err ~2^-12, B single fp16)
// PASSES=3: acc = ah*bh + al*bh + ah*bl (err ~2^-22)
// MODE 0: C[m,n] = acc + bias[n]
// MODE 1: sc[m] += sum_n tanh(acc + bias[n]) * hidden[m>>7, n]
constexpr int GM = 128, GN = 128;
constexpr int ROWB = 80;                   // fp16 tile row stride (64B + pad)
constexpr int HTILE = 128 * ROWB;          // 10240 B per fp16 tile
constexpr int STG = 128 * 128;             // 16384 B per fp32 staging tile
constexpr int STG_STAGE = 2 * STG;         // A + B per stage
constexpr uint32_t HF_BASE = 2 * STG_STAGE;    // 65536 (2 staging stages)
constexpr uint32_t AH_O = HF_BASE;
constexpr uint32_t AL_O = HF_BASE + HTILE;
constexpr uint32_t BH_O = HF_BASE + 2 * HTILE;
constexpr uint32_t BL_O = HF_BASE + 3 * HTILE;
constexpr int MMA_SMEM = HF_BASE + 4 * HTILE;  // 106496 B

__device__ __forceinline__ uint32_t stg_sw(int row, int byteInRow) {
    uint32_t off = (uint32_t)(row * 128 + byteInRow);
    return off ^ ((uint32_t)(row & 7) << 4);
}

template <int MODE, int PASSES>
__global__ void __launch_bounds__(256, 2)
mma_gemm(const float* __restrict__ Af, const float* __restrict__ Bf,
         const float* __restrict__ bias, float* __restrict__ C,
         int M, int N, int K,
         const float* __restrict__ hidden, float* __restrict__ scOut) {
    extern __shared__ __align__(16) char smem[];
    const int t = threadIdx.x;
    const int lane = t & 31;
    const int wid = t >> 5;
    const int wm = wid & 3;      // 4 x 32-row slabs
    const int wn = wid >> 2;     // 2 x 64-col slabs
    const int m0 = blockIdx.y * GM, n0 = blockIdx.x * GN;
    const uint32_t sb = smem_u32(smem);

    float acc[2][8][4];
#pragma unroll
    for (int i = 0; i < 2; i++)
#pragma unroll
        for (int j = 0; j < 8; j++)
#pragma unroll
            for (int r = 0; r < 4; r++) acc[i][j][r] = 0.f;

    const int KT = K / 32;
    const int cr = t >> 2;              // rows cr, cr+64
    const int cq = t & 3;               // 32B column quad

    auto issue_load = [&](int it) {
        const int kk = it * 32;
        uint32_t stA = sb + (uint32_t)(it & 1) * STG_STAGE;
        uint32_t stB = stA + STG;
        const float* Ap = Af + (size_t)(m0 + cr) * K + kk + cq * 8;
        const float* Bp = Bf + (size_t)(n0 + cr) * K + kk + cq * 8;
#pragma unroll
        for (int h = 0; h < 2; h++) {
            int row = cr + h * 64;
            cp_async16(stA + stg_sw(row, cq * 32),      Ap + (size_t)h * 64 * K);
            cp_async16(stA + stg_sw(row, cq * 32 + 16), Ap + (size_t)h * 64 * K + 4);
            cp_async16(stB + stg_sw(row, cq * 32),      Bp + (size_t)h * 64 * K);
            cp_async16(stB + stg_sw(row, cq * 32 + 16), Bp + (size_t)h * 64 * K + 4);
        }
        cp_commit();
    };

    const int a_row = (lane & 15);
    const int a_kof = ((lane >> 4) & 1) * 16;
    const int b_row = ((lane >> 4) << 3) + (lane & 7);
    const int b_kof = ((lane >> 3) & 1) * 16;
    const int g = lane >> 2, q = lane & 3;

    issue_load(0);
    if (KT > 1) issue_load(1);

    for (int it = 0; it < KT; ++it) {
        if (it + 1 < KT) cp_wait<1>(); else cp_wait<0>();
        __syncthreads();   // staging ready; prior-iter ldmatrix done everywhere

        // convert fp32 staging -> fp16 tiles (A: hi+lo, B: hi (+lo if PASSES==3))
        {
            uint32_t stAo = (uint32_t)(it & 1) * STG_STAGE;
            uint32_t stBo = stAo + STG;
#pragma unroll
            for (int h = 0; h < 2; h++) {
                int row = cr + h * 64;
                uint32_t so0 = stg_sw(row, cq * 32);
                uint32_t so1 = stg_sw(row, cq * 32 + 16);
                uint32_t dof = (uint32_t)(row * ROWB + cq * 16);
                // A hi/lo
                float4 va0 = *reinterpret_cast<const float4*>(smem + stAo + so0);
                float4 va1 = *reinterpret_cast<const float4*>(smem + stAo + so1);
                uint32_t h0, h1, h2, h3, l0, l1, l2, l3;
                split2h(make_float2(va0.x, va0.y), h0, l0);
                split2h(make_float2(va0.z, va0.w), h1, l1);
                split2h(make_float2(va1.x, va1.y), h2, l2);
                split2h(make_float2(va1.z, va1.w), h3, l3);
                *reinterpret_cast<uint4*>(smem + AH_O + dof) = make_uint4(h0, h1, h2, h3);
                *reinterpret_cast<uint4*>(smem + AL_O + dof) = make_uint4(l0, l1, l2, l3);
                // B
                float4 vb0 = *reinterpret_cast<const float4*>(smem + stBo + so0);
                float4 vb1 = *reinterpret_cast<const float4*>(smem + stBo + so1);
                if (PASSES == 3) {
                    split2h(make_float2(vb0.x, vb0.y), h0, l0);
                    split2h(make_float2(vb0.z, vb0.w), h1, l1);
                    split2h(make_float2(vb1.x, vb1.y), h2, l2);
                    split2h(make_float2(vb1.z, vb1.w), h3, l3);
                    *reinterpret_cast<uint4*>(smem + BH_O + dof) = make_uint4(h0, h1, h2, h3);
                    *reinterpret_cast<uint4*>(smem + BL_O + dof) = make_uint4(l0, l1, l2, l3);
                } else {
                    h0 = f2h2(make_float2(vb0.x, vb0.y));
                    h1 = f2h2(make_float2(vb0.z, vb0.w));
                    h2 = f2h2(make_float2(vb1.x, vb1.y));
                    h3 = f2h2(make_float2(vb1.z, vb1.w));
                    *reinterpret_cast<uint4*>(smem + BH_O + dof) = make_uint4(h0, h1, h2, h3);
                }
            }
        }
        __syncthreads();   // fp16 tiles visible; staging free
        if (it + 2 < KT) issue_load(it + 2);

#pragma unroll
        for (int ks = 0; ks < 2; ks++) {
            const int kb = ks * 32;   // byte offset within fp16 tile row
            // B hi fragments for this warp's 64 columns (+ lo if PASSES==3)
            uint32_t bh[8][2], bl[8][2];
#pragma unroll
            for (int njp = 0; njp < 4; njp++) {
                uint32_t addr = sb + BH_O + (wn * 64 + njp * 16 + b_row) * ROWB + kb + b_kof;
                uint32_t q0, q1, q2, q3;
                ldmx4(q0, q1, q2, q3, addr);
                bh[njp * 2][0] = q0; bh[njp * 2][1] = q1;
                bh[njp * 2 + 1][0] = q2; bh[njp * 2 + 1][1] = q3;
                if (PASSES == 3) {
                    uint32_t addr2 = sb + BL_O + (wn * 64 + njp * 16 + b_row) * ROWB + kb + b_kof;
                    ldmx4(q0, q1, q2, q3, addr2);
                    bl[njp * 2][0] = q0; bl[njp * 2][1] = q1;
                    bl[njp * 2 + 1][0] = q2; bl[njp * 2 + 1][1] = q3;
                }
            }
#pragma unroll
            for (int mi = 0; mi < 2; mi++) {
                const uint32_t arow_off = (wm * 32 + mi * 16 + a_row) * ROWB + kb + a_kof;
                uint32_t ah[4], al[4];
                ldmx4(ah[0], ah[1], ah[2], ah[3], sb + AH_O + arow_off);
                ldmx4(al[0], al[1], al[2], al[3], sb + AL_O + arow_off);
#pragma unroll
                for (int nj = 0; nj < 8; nj++) mma16816(acc[mi][nj], ah, bh[nj]);
#pragma unroll
                for (int nj = 0; nj < 8; nj++) mma16816(acc[mi][nj], al, bh[nj]);
                if (PASSES == 3) {
#pragma unroll
                    for (int nj = 0; nj < 8; nj++) mma16816(acc[mi][nj], ah, bl[nj]);
                }
            }
        }
    }

    // ---------------- epilogue ----------------
    if (MODE == 0) {
#pragma unroll
        for (int mi = 0; mi < 2; mi++) {
            int row0 = m0 + wm * 32 + mi * 16 + g;
            int row1 = row0 + 8;
#pragma unroll
            for (int nj = 0; nj < 8; nj++) {
                int col = n0 + wn * 64 + nj * 8 + 2 * q;
                float b0 = bias[col], b1 = bias[col + 1];
                float2 o0 = make_float2(acc[mi][nj][0] + b0, acc[mi][nj][1] + b1);
                float2 o1 = make_float2(acc[mi][nj][2] + b0, acc[mi][nj][3] + b1);
                *reinterpret_cast<float2*>(&C[(size_t)row0 * N + col]) = o0;
                *reinterpret_cast<float2*>(&C[(size_t)row1 * N + col]) = o1;
            }
        }
    } else {
        const int b = m0 >> 7;   // GM == S_
#pragma unroll
        for (int mi = 0; mi < 2; mi++) {
            float p0 = 0.f, p1 = 0.f;
#pragma unroll
            for (int nj = 0; nj < 8; nj++) {
                int col = n0 + wn * 64 + nj * 8 + 2 * q;
                float bz0 = bias[col], bz1 = bias[col + 1];
                float hv0 = hidden[b * H_ + col], hv1 = hidden[b * H_ + col + 1];
                p0 = fmaf(tanhf(acc[mi][nj][0] + bz0), hv0, p0);
                p0 = fmaf(tanhf(acc[mi][nj][1] + bz1), hv1, p0);
                p1 = fmaf(tanhf(acc[mi][nj][2] + bz0), hv0, p1);
                p1 = fmaf(tanhf(acc[mi][nj][3] + bz1), hv1, p1);
            }
            p0 += __shfl_xor_sync(0xffffffffu, p0, 1);
            p0 += __shfl_xor_sync(0xffffffffu, p0, 2);
            p1 += __shfl_xor_sync(0xffffffffu, p1, 1);
            p1 += __shfl_xor_sync(0xffffffffu, p1, 2);
            if (q == 0) {
                int row = m0 + wm * 32 + mi * 16 + g;
                atomicAdd(&scOut[row], p0);
                atomicAdd(&scOut[row + 8], p1);
            }
        }
    }
}

// ---------------- GRU ----------------
__global__ void gru_kernel(const float* __restrict__ prev,
                           float* __restrict__ outHidden) {
    int idx = blockIdx.x * blockDim.x + threadIdx.x;
    int b = idx >> 9, h = idx & (H_ - 1);
    const float* gi = g_gi + (size_t)b * G_;
    const float* gh = g_gh + (size_t)b * G_;
    float ir = gi[h], iz = gi[h + H_], inn = gi[h + 2 * H_];
    float hr = gh[h], hz = gh[h + H_], hn = gh[h + 2 * H_];
    float r = 1.f / (1.f + expf(-(ir + hr)));
    float z = 1.f / (1.f + expf(-(iz + hz)));
    float n = tanhf(inn + r * hn);
    float hv = (1.f - z) * n + z * prev[idx];
    g_hidden[idx] = hv;
    outHidden[idx] = hv;
}

// ---------------- softmax (online max+sum) ----------------
__global__ void __launch_bounds__(512)
softmax_kernel(float* __restrict__ pred, const int* __restrict__ src,
               const int* __restrict__ ids) {
    __shared__ float s_lc[S_];
    __shared__ float s_m[512];
    __shared__ float s_s[512];
    __shared__ int s_cnt;
    const int b = blockIdx.x, t = threadIdx.x;
    float* row = pred + (size_t)b * V_;

    if (t == 0) s_cnt = 0;
    if (t < S_) {
        float mask = (src[b * S_ + t] == 0) ? -1000.f : 0.f;
        s_lc[t] = tanhf(g_sc[b * S_ + t] + mask);
    }
    __syncthreads();

    float m = -1e30f, s = 0.f;
    for (int v = t; v < V_; v += 512) {
        float x = row[v];
        float nm = fmaxf(m, x);
        s = s * __expf(m - nm) + __expf(x - nm);
        m = nm;
    }
    if (t < S_) {
        float x = s_lc[t];
        float nm = fmaxf(m, x);
        s = s * __expf(m - nm) + __expf(x - nm);
        m = nm;
    }
    s_m[t] = m; s_s[t] = s;
    __syncthreads();
    for (int o = 256; o; o >>= 1) {
        if (t < o) {
            float m1 = s_m[t], m2 = s_m[t + o];
            float nm = fmaxf(m1, m2);
            s_s[t] = s_s[t] * __expf(m1 - nm) + s_s[t + o] * __expf(m2 - nm);
            s_m[t] = nm;
        }
        __syncthreads();
    }
    float gmax = s_m[0];
    float inv = 1.f / s_s[0];

    for (int v = t; v < V_; v += 512) row[v] = __expf(row[v] - gmax) * inv;

    int id = ids[b];
    if (t < S_ && src[b * S_ + t] == id) atomicAdd(&s_cnt, 1);
    __syncthreads();

    if (t < S_) {
        float pc = __expf(s_lc[t] - gmax) * inv;
        atomicAdd(&row[src[b * S_ + t]], pc);
        float eq = (src[b * S_ + t] == id) ? 1.f : 0.f;
        g_attn[b * S_ + t] = pc * eq / fmaxf((float)s_cnt, 1.f);
    }
}

__global__ void __launch_bounds__(256)
weighted_kernel(const float* __restrict__ enc, float* __restrict__ outW) {
    __shared__ float s_a[S_];
    const int b = blockIdx.x, t = threadIdx.x;
    if (t < S_) s_a[t] = g_attn[b * S_ + t];
    __syncthreads();
    float4 acc = make_float4(0.f, 0.f, 0.f, 0.f);
    const float4* e4 = reinterpret_cast<const float4*>(enc + (size_t)b * S_ * (2 * H_));
    for (int s = 0; s < S_; s++) {
        float w = s_a[s];
        if (w != 0.f) {
            float4 e = e4[s * 256 + t];
            acc.x = fmaf(w, e.x, acc.x); acc.y = fmaf(w, e.y, acc.y);
            acc.z = fmaf(w, e.z, acc.z); acc.w = fmaf(w, e.w, acc.w);
        }
    }
    reinterpret_cast<float4*>(outW)[b * 256 + t] = acc;
}

// ---------------- launch ----------------
extern "C" void kernel_launch(void* const* d_in, const int* in_sizes, int n_in,
                              void* d_out, int out_size) {
    const int*   input_ids = (const int*)d_in[0];
    const float* encoded   = (const float*)d_in[1];
    const int*   src       = (const int*)d_in[2];
    const float* prev      = (const float*)d_in[3];
    const float* weighted  = (const float*)d_in[4];
    const float* embed_w   = (const float*)d_in[6];
    const float* w_ih      = (const float*)d_in[7];
    const float* w_hh      = (const float*)d_in[8];
    const float* b_ih      = (const float*)d_in[9];
    const float* b_hh      = (const float*)d_in[10];
    const float* Wo_w      = (const float*)d_in[13];
    const float* Wo_b      = (const float*)d_in[14];
    const float* Wc_w      = (const float*)d_in[15];
    const float* Wc_b      = (const float*)d_in[16];

    float* pred        = (float*)d_out;
    float* outHidden   = pred + (size_t)B_ * V_;
    float* outWeighted = outHidden + (size_t)B_ * H_;

    float *px, *pgi, *pgh, *phid, *psc;
    cudaGetSymbolAddress((void**)&px,   g_x);
    cudaGetSymbolAddress((void**)&pgi,  g_gi);
    cudaGetSymbolAddress((void**)&pgh,  g_gh);
    cudaGetSymbolAddress((void**)&phid, g_hidden);
    cudaGetSymbolAddress((void**)&psc,  g_sc);

    cudaFuncSetAttribute(mma_gemm<0, 2>, cudaFuncAttributeMaxDynamicSharedMemorySize, MMA_SMEM);
    cudaFuncSetAttribute(mma_gemm<0, 3>, cudaFuncAttributeMaxDynamicSharedMemorySize, MMA_SMEM);
    cudaFuncSetAttribute(mma_gemm<1, 2>, cudaFuncAttributeMaxDynamicSharedMemorySize, MMA_SMEM);

    // x = concat(embed[ids], weighted)
    build_x_kernel<<<(B_ * IN_) / 256, 256>>>(input_ids, embed_w, weighted);

    // gi / gh: 3-pass (protects hidden output accuracy; small GEMMs)
    mma_gemm<0, 3><<<dim3(G_ / GN, B_ / GM), 256, MMA_SMEM>>>(
        px, w_ih, b_ih, pgi, B_, G_, IN_, nullptr, nullptr);
    mma_gemm<0, 3><<<dim3(G_ / GN, B_ / GM), 256, MMA_SMEM>>>(
        prev, w_hh, b_hh, pgh, B_, G_, H_, nullptr, nullptr);

    gru_kernel<<<(B_ * H_) / 256, 256>>>(prev, outHidden);

    // score_g = hidden @ Wo^T + Wo_b  (2-pass fp16 split)
    mma_gemm<0, 2><<<dim3(V_ / GN, B_ / GM), 256, MMA_SMEM>>>(
        phid, Wo_w, Wo_b, pred, B_, V_, H_, nullptr, nullptr);

    // sc = einsum(tanh(enc @ Wc^T + Wc_b), hidden)  (2-pass fp16 split)
    zero_sc_kernel<<<(B_ * S_) / 256, 256>>>();
    mma_gemm<1, 2><<<dim3(H_ / GN, (B_ * S_) / GM), 256, MMA_SMEM>>>(
        encoded, Wc_w, Wc_b, nullptr, B_ * S_, H_, 2 * H_, phid, psc);

    softmax_kernel<<<B_, 512>>>(pred, src, input_ids);
    weighted_kernel<<<B_, 256>>>(encoded, outWeighted);

    (void)in_sizes; (void)n_in; (void)out_size;
}

// round 8
// speedup vs baseline: 1.8522x; 1.3046x over previous
#include <cuda_runtime.h>
#include <cuda_fp16.h>
#include <math.h>
#include <stdint.h>

namespace {
constexpr int B_ = 256;
constexpr int S_ = 128;
constexpr int H_ = 512;
constexpr int E_ = 512;
constexpr int V_ = 32000;
constexpr int IN_ = E_ + 2 * H_;   // 1536
constexpr int G_ = 3 * H_;         // 1536
}

// ---------------- static scratch ----------------
__device__ float g_gi[B_ * G_];
__device__ float g_gh[B_ * G_];
__device__ float g_hidden[B_ * H_];
__device__ float g_sc[B_ * S_];
__device__ float g_attn[B_ * S_];
__device__ __half g_x_hi[B_ * IN_];
__device__ __half g_x_lo[B_ * IN_];
__device__ __half g_prev_hi[B_ * H_];
__device__ __half g_prev_lo[B_ * H_];
__device__ __half g_wih_hi[G_ * IN_];
__device__ __half g_whh_hi[G_ * H_];
__device__ __half g_wc_hi[H_ * 2 * H_];

// ---------------- helpers ----------------
__device__ __forceinline__ void cp_async16(uint32_t s, const void* g) {
    asm volatile("cp.async.cg.shared.global [%0], [%1], 16;\n"
                 :: "r"(s), "l"(g) : "memory");
}
__device__ __forceinline__ void cp_commit() {
    asm volatile("cp.async.commit_group;\n" ::: "memory");
}
template <int N>
__device__ __forceinline__ void cp_wait() {
    asm volatile("cp.async.wait_group %0;\n" :: "n"(N) : "memory");
}
__device__ __forceinline__ uint32_t smem_u32(const void* p) {
    uint32_t a;
    asm("{ .reg .u64 t; cvta.to.shared.u64 t, %1; cvt.u32.u64 %0, t; }"
        : "=r"(a) : "l"(p));
    return a;
}
__device__ __forceinline__ void ldmx4(uint32_t& r0, uint32_t& r1, uint32_t& r2,
                                      uint32_t& r3, uint32_t addr) {
    asm volatile("ldmatrix.sync.aligned.m8n8.x4.shared.b16 {%0,%1,%2,%3}, [%4];\n"
                 : "=r"(r0), "=r"(r1), "=r"(r2), "=r"(r3) : "r"(addr));
}
__device__ __forceinline__ void mma16816(float* d, const uint32_t* a,
                                         const uint32_t* b) {
    asm volatile(
        "mma.sync.aligned.m16n8k16.row.col.f32.f16.f16.f32 "
        "{%0,%1,%2,%3}, {%4,%5,%6,%7}, {%8,%9}, {%0,%1,%2,%3};\n"
        : "+f"(d[0]), "+f"(d[1]), "+f"(d[2]), "+f"(d[3])
        : "r"(a[0]), "r"(a[1]), "r"(a[2]), "r"(a[3]), "r"(b[0]), "r"(b[1]));
}
__device__ __forceinline__ uint32_t f2h2(float2 f) {
    __half2 h = __float22half2_rn(f);
    return *reinterpret_cast<uint32_t*>(&h);
}
__device__ __forceinline__ void split2h(float2 f, uint32_t& hi, uint32_t& lo) {
    hi = f2h2(f);
    __half2 hh = *reinterpret_cast<__half2*>(&hi);
    float2 fh = __half22float2(hh);
    lo = f2h2(make_float2(f.x - fh.x, f.y - fh.y));
}

// ---------------- elementwise kernels ----------------
__global__ void build_x_split_kernel(const int* __restrict__ ids,
                                     const float* __restrict__ emb,
                                     const float* __restrict__ weighted) {
    int idx = blockIdx.x * blockDim.x + threadIdx.x;  // < B*IN
    int b = idx / IN_;
    int j = idx - b * IN_;
    float v = (j < E_) ? emb[(size_t)ids[b] * E_ + j]
                       : weighted[b * (2 * H_) + (j - E_)];
    __half h = __float2half_rn(v);
    g_x_hi[idx] = h;
    g_x_lo[idx] = __float2half_rn(v - __half2float(h));
}

__global__ void split_hilo_kernel(const float* __restrict__ s,
                                  __half* __restrict__ hi,
                                  __half* __restrict__ lo, int n) {
    int i = (blockIdx.x * blockDim.x + threadIdx.x) * 4;
    if (i >= n) return;
    float4 v = *reinterpret_cast<const float4*>(s + i);
    uint32_t h0, h1, l0, l1;
    split2h(make_float2(v.x, v.y), h0, l0);
    split2h(make_float2(v.z, v.w), h1, l1);
    *reinterpret_cast<uint2*>(hi + i) = make_uint2(h0, h1);
    *reinterpret_cast<uint2*>(lo + i) = make_uint2(l0, l1);
}

__global__ void split_hi_kernel(const float* __restrict__ s,
                                __half* __restrict__ hi, int n) {
    int i = (blockIdx.x * blockDim.x + threadIdx.x) * 4;
    if (i >= n) return;
    float4 v = *reinterpret_cast<const float4*>(s + i);
    uint32_t h0 = f2h2(make_float2(v.x, v.y));
    uint32_t h1 = f2h2(make_float2(v.z, v.w));
    *reinterpret_cast<uint2*>(hi + i) = make_uint2(h0, h1);
}

__global__ void zero_kernel(float* __restrict__ p) {
    p[blockIdx.x * blockDim.x + threadIdx.x] = 0.f;
}

// ---------------- common GEMM constants ----------------
constexpr int GM = 128, GN = 128;
constexpr int ROWB = 80;                   // fp16 tile row stride
constexpr int HTILE = 128 * ROWB;          // 10240 B
constexpr int STG_A = 128 * 128;           // 16384 B (one fp32 tile)

// =====================================================================
// Gates kernel: gi = x @ Wih^T + b_ih (split-K over z=0..2, atomicAdd)
//               gh = prev @ Whh^T + b_hh (z=3, direct store)
// All operands pre-split fp16 (A hi/lo, B hi), 2-pass. N = G_ fixed.
// SMEM: 3 stages x 3 tiles = 92160 B.
// =====================================================================
constexpr int GATES_SMEM = 3 * 3 * HTILE;

__global__ void __launch_bounds__(256, 2)
mma_gates(const float* __restrict__ b_ih, const float* __restrict__ b_hh) {
    extern __shared__ __align__(16) char smem[];
    const int t = threadIdx.x;
    const int lane = t & 31;
    const int wid = t >> 5;
    const int wm = wid & 3, wn = wid >> 2;
    const int m0 = blockIdx.y * GM, n0 = blockIdx.x * GN;
    const int z = blockIdx.z;
    const uint32_t sb = smem_u32(smem);

    const __half *Ah, *Al, *Bh;
    const float* bias;
    float* C;
    int K, kstart;
    bool atomic, addBias;
    if (z < 3) {
        Ah = g_x_hi; Al = g_x_lo; Bh = g_wih_hi;
        bias = b_ih; C = g_gi; K = IN_; kstart = z * 512;
        atomic = true; addBias = (z == 0);
    } else {
        Ah = g_prev_hi; Al = g_prev_lo; Bh = g_whh_hi;
        bias = b_hh; C = g_gh; K = H_; kstart = 0;
        atomic = false; addBias = true;
    }
    const int KCH = 16;   // 16 chunks of 32 for both branches

    float acc[2][8][4];
#pragma unroll
    for (int i = 0; i < 2; i++)
#pragma unroll
        for (int j = 0; j < 8; j++)
#pragma unroll
            for (int r = 0; r < 4; r++) acc[i][j][r] = 0.f;

    auto issue = [&](int it) {
        uint32_t st = sb + (uint32_t)(it % 3) * (3 * HTILE);
        int kk = kstart + it * 32;
#pragma unroll
        for (int i = 0; i < 2; i++) {
            int idx = t + i * 256;
            int row = idx >> 2, col = idx & 3;
            uint32_t so = (uint32_t)(row * ROWB + col * 16);
            const size_t ga = (size_t)(m0 + row) * K + kk + col * 8;
            const size_t gb = (size_t)(n0 + row) * K + kk + col * 8;
            cp_async16(st + so, Ah + ga);
            cp_async16(st + HTILE + so, Al + ga);
            cp_async16(st + 2 * HTILE + so, Bh + gb);
        }
        cp_commit();
    };

    const int a_row = (lane & 15);
    const int a_kof = ((lane >> 4) & 1) * 16;
    const int b_row = ((lane >> 4) << 3) + (lane & 7);
    const int b_kof = ((lane >> 3) & 1) * 16;
    const int g = lane >> 2, q = lane & 3;

    issue(0); issue(1);
    for (int it = 0; it < KCH; ++it) {
        if (it + 1 < KCH) cp_wait<1>(); else cp_wait<0>();
        __syncthreads();
        if (it + 2 < KCH) issue(it + 2);
        const uint32_t st = sb + (uint32_t)(it % 3) * (3 * HTILE);
#pragma unroll
        for (int ks = 0; ks < 2; ks++) {
            const int kb = ks * 32;
            uint32_t bh[8][2];
#pragma unroll
            for (int njp = 0; njp < 4; njp++) {
                uint32_t addr = st + 2 * HTILE + (wn * 64 + njp * 16 + b_row) * ROWB + kb + b_kof;
                uint32_t q0, q1, q2, q3;
                ldmx4(q0, q1, q2, q3, addr);
                bh[njp * 2][0] = q0; bh[njp * 2][1] = q1;
                bh[njp * 2 + 1][0] = q2; bh[njp * 2 + 1][1] = q3;
            }
#pragma unroll
            for (int mi = 0; mi < 2; mi++) {
                const uint32_t aro = (wm * 32 + mi * 16 + a_row) * ROWB + kb + a_kof;
                uint32_t ah[4], al[4];
                ldmx4(ah[0], ah[1], ah[2], ah[3], st + aro);
                ldmx4(al[0], al[1], al[2], al[3], st + HTILE + aro);
#pragma unroll
                for (int nj = 0; nj < 8; nj++) mma16816(acc[mi][nj], ah, bh[nj]);
#pragma unroll
                for (int nj = 0; nj < 8; nj++) mma16816(acc[mi][nj], al, bh[nj]);
            }
        }
    }

#pragma unroll
    for (int mi = 0; mi < 2; mi++) {
        int row0 = m0 + wm * 32 + mi * 16 + g;
        int row1 = row0 + 8;
#pragma unroll
        for (int nj = 0; nj < 8; nj++) {
            int col = n0 + wn * 64 + nj * 8 + 2 * q;
            float b0 = addBias ? bias[col] : 0.f;
            float b1 = addBias ? bias[col + 1] : 0.f;
            if (atomic) {
                atomicAdd(&C[(size_t)row0 * G_ + col],     acc[mi][nj][0] + b0);
                atomicAdd(&C[(size_t)row0 * G_ + col + 1], acc[mi][nj][1] + b1);
                atomicAdd(&C[(size_t)row1 * G_ + col],     acc[mi][nj][2] + b0);
                atomicAdd(&C[(size_t)row1 * G_ + col + 1], acc[mi][nj][3] + b1);
            } else {
                float2 o0 = make_float2(acc[mi][nj][0] + b0, acc[mi][nj][1] + b1);
                float2 o1 = make_float2(acc[mi][nj][2] + b0, acc[mi][nj][3] + b1);
                *reinterpret_cast<float2*>(&C[(size_t)row0 * G_ + col]) = o0;
                *reinterpret_cast<float2*>(&C[(size_t)row1 * G_ + col]) = o1;
            }
        }
    }
}

// =====================================================================
// Mixed GEMM: C[M,N] = A[M,K] @ W[N,K]^T, 2-pass fp16 split.
// A: fp32, cp.async-staged and converted in-kernel to hi/lo tiles.
// B: PRE_B ? pre-split fp16-hi cp.async'd into triple-buffered tiles
//          : fp32 staged + converted (hi only).
// MODE 0: C[m,n] = acc + bias[n]
// MODE 1: sc[m] += sum_n tanh(acc + bias[n]) * hidden[m>>7, n]
// =====================================================================
template <int MODE, bool PRE_B>
__global__ void __launch_bounds__(256, 2)
mma_gemm(const float* __restrict__ Af, const float* __restrict__ Bf,
         const __half* __restrict__ Bh16,
         const float* __restrict__ bias, float* __restrict__ C,
         int M, int N, int K,
         const float* __restrict__ hidden, float* __restrict__ scOut) {
    extern __shared__ __align__(16) char smem[];
    // layout
    constexpr uint32_t STG_STAGE = PRE_B ? STG_A : 2 * STG_A;
    constexpr uint32_t AH_O = 2 * STG_STAGE;
    constexpr uint32_t AL_O = AH_O + HTILE;
    constexpr uint32_t BH_O = AL_O + HTILE;

    const int t = threadIdx.x;
    const int lane = t & 31;
    const int wid = t >> 5;
    const int wm = wid & 3, wn = wid >> 2;
    const int m0 = blockIdx.y * GM, n0 = blockIdx.x * GN;
    const uint32_t sb = smem_u32(smem);

    float acc[2][8][4];
#pragma unroll
    for (int i = 0; i < 2; i++)
#pragma unroll
        for (int j = 0; j < 8; j++)
#pragma unroll
            for (int r = 0; r < 4; r++) acc[i][j][r] = 0.f;

    const int KT = K / 32;
    const int cr = t >> 2;
    const int cq = t & 3;

    auto issue_load = [&](int it) {
        const int kk = it * 32;
        uint32_t stA = sb + (uint32_t)(it & 1) * STG_STAGE;
        const float* Ap = Af + (size_t)(m0 + cr) * K + kk + cq * 8;
#pragma unroll
        for (int h = 0; h < 2; h++) {
            int row = cr + h * 64;
            uint32_t off = (uint32_t)(row * 128 + cq * 32);
            off ^= ((uint32_t)(row & 7) << 4);
            cp_async16(stA + off, Ap + (size_t)h * 64 * K);
            uint32_t off2 = (uint32_t)(row * 128 + cq * 32 + 16);
            off2 ^= ((uint32_t)(row & 7) << 4);
            cp_async16(stA + off2, Ap + (size_t)h * 64 * K + 4);
        }
        if (PRE_B) {
            uint32_t bt = sb + BH_O + (uint32_t)(it % 3) * HTILE;
#pragma unroll
            for (int i = 0; i < 2; i++) {
                int idx = t + i * 256;
                int row = idx >> 2, col = idx & 3;
                cp_async16(bt + (uint32_t)(row * ROWB + col * 16),
                           Bh16 + (size_t)(n0 + row) * K + kk + col * 8);
            }
        } else {
            uint32_t stB = stA + STG_A;
            const float* Bp = Bf + (size_t)(n0 + cr) * K + kk + cq * 8;
#pragma unroll
            for (int h = 0; h < 2; h++) {
                int row = cr + h * 64;
                uint32_t off = (uint32_t)(row * 128 + cq * 32);
                off ^= ((uint32_t)(row & 7) << 4);
                cp_async16(stB + off, Bp + (size_t)h * 64 * K);
                uint32_t off2 = (uint32_t)(row * 128 + cq * 32 + 16);
                off2 ^= ((uint32_t)(row & 7) << 4);
                cp_async16(stB + off2, Bp + (size_t)h * 64 * K + 4);
            }
        }
        cp_commit();
    };

    const int a_row = (lane & 15);
    const int a_kof = ((lane >> 4) & 1) * 16;
    const int b_row = ((lane >> 4) << 3) + (lane & 7);
    const int b_kof = ((lane >> 3) & 1) * 16;
    const int g = lane >> 2, q = lane & 3;

    issue_load(0);
    if (KT > 1) issue_load(1);

    for (int it = 0; it < KT; ++it) {
        if (it + 1 < KT) cp_wait<1>(); else cp_wait<0>();
        __syncthreads();

        // convert A (and B if staged) from fp32 staging to fp16 tiles
        {
            uint32_t stAo = (uint32_t)(it & 1) * STG_STAGE;
#pragma unroll
            for (int h = 0; h < 2; h++) {
                int row = cr + h * 64;
                uint32_t so0 = (uint32_t)(row * 128 + cq * 32) ^ ((uint32_t)(row & 7) << 4);
                uint32_t so1 = (uint32_t)(row * 128 + cq * 32 + 16) ^ ((uint32_t)(row & 7) << 4);
                uint32_t dof = (uint32_t)(row * ROWB + cq * 16);
                float4 va0 = *reinterpret_cast<const float4*>(smem + stAo + so0);
                float4 va1 = *reinterpret_cast<const float4*>(smem + stAo + so1);
                uint32_t h0, h1, h2, h3, l0, l1, l2, l3;
                split2h(make_float2(va0.x, va0.y), h0, l0);
                split2h(make_float2(va0.z, va0.w), h1, l1);
                split2h(make_float2(va1.x, va1.y), h2, l2);
                split2h(make_float2(va1.z, va1.w), h3, l3);
                *reinterpret_cast<uint4*>(smem + AH_O + dof) = make_uint4(h0, h1, h2, h3);
                *reinterpret_cast<uint4*>(smem + AL_O + dof) = make_uint4(l0, l1, l2, l3);
                if (!PRE_B) {
                    float4 vb0 = *reinterpret_cast<const float4*>(smem + stAo + STG_A + so0);
                    float4 vb1 = *reinterpret_cast<const float4*>(smem + stAo + STG_A + so1);
                    h0 = f2h2(make_float2(vb0.x, vb0.y));
                    h1 = f2h2(make_float2(vb0.z, vb0.w));
                    h2 = f2h2(make_float2(vb1.x, vb1.y));
                    h3 = f2h2(make_float2(vb1.z, vb1.w));
                    *reinterpret_cast<uint4*>(smem + BH_O + dof) = make_uint4(h0, h1, h2, h3);
                }
            }
        }
        __syncthreads();
        if (it + 2 < KT) issue_load(it + 2);

        const uint32_t bTile = PRE_B ? (BH_O + (uint32_t)(it % 3) * HTILE) : BH_O;
#pragma unroll
        for (int ks = 0; ks < 2; ks++) {
            const int kb = ks * 32;
            uint32_t bh[8][2];
#pragma unroll
            for (int njp = 0; njp < 4; njp++) {
                uint32_t addr = sb + bTile + (wn * 64 + njp * 16 + b_row) * ROWB + kb + b_kof;
                uint32_t q0, q1, q2, q3;
                ldmx4(q0, q1, q2, q3, addr);
                bh[njp * 2][0] = q0; bh[njp * 2][1] = q1;
                bh[njp * 2 + 1][0] = q2; bh[njp * 2 + 1][1] = q3;
            }
#pragma unroll
            for (int mi = 0; mi < 2; mi++) {
                const uint32_t aro = (wm * 32 + mi * 16 + a_row) * ROWB + kb + a_kof;
                uint32_t ah[4], al[4];
                ldmx4(ah[0], ah[1], ah[2], ah[3], sb + AH_O + aro);
                ldmx4(al[0], al[1], al[2], al[3], sb + AL_O + aro);
#pragma unroll
                for (int nj = 0; nj < 8; nj++) mma16816(acc[mi][nj], ah, bh[nj]);
#pragma unroll
                for (int nj = 0; nj < 8; nj++) mma16816(acc[mi][nj], al, bh[nj]);
            }
        }
    }

    // ---------------- epilogue ----------------
    if (MODE == 0) {
#pragma unroll
        for (int mi = 0; mi < 2; mi++) {
            int row0 = m0 + wm * 32 + mi * 16 + g;
            int row1 = row0 + 8;
#pragma unroll
            for (int nj = 0; nj < 8; nj++) {
                int col = n0 + wn * 64 + nj * 8 + 2 * q;
                float b0 = bias[col], b1 = bias[col + 1];
                float2 o0 = make_float2(acc[mi][nj][0] + b0, acc[mi][nj][1] + b1);
                float2 o1 = make_float2(acc[mi][nj][2] + b0, acc[mi][nj][3] + b1);
                *reinterpret_cast<float2*>(&C[(size_t)row0 * N + col]) = o0;
                *reinterpret_cast<float2*>(&C[(size_t)row1 * N + col]) = o1;
            }
        }
    } else {
        const int b = m0 >> 7;   // GM == S_
#pragma unroll
        for (int mi = 0; mi < 2; mi++) {
            float p0 = 0.f, p1 = 0.f;
#pragma unroll
            for (int nj = 0; nj < 8; nj++) {
                int col = n0 + wn * 64 + nj * 8 + 2 * q;
                float bz0 = bias[col], bz1 = bias[col + 1];
                float hv0 = hidden[b * H_ + col], hv1 = hidden[b * H_ + col + 1];
                p0 = fmaf(tanhf(acc[mi][nj][0] + bz0), hv0, p0);
                p0 = fmaf(tanhf(acc[mi][nj][1] + bz1), hv1, p0);
                p1 = fmaf(tanhf(acc[mi][nj][2] + bz0), hv0, p1);
                p1 = fmaf(tanhf(acc[mi][nj][3] + bz1), hv1, p1);
            }
            p0 += __shfl_xor_sync(0xffffffffu, p0, 1);
            p0 += __shfl_xor_sync(0xffffffffu, p0, 2);
            p1 += __shfl_xor_sync(0xffffffffu, p1, 1);
            p1 += __shfl_xor_sync(0xffffffffu, p1, 2);
            if (q == 0) {
                int row = m0 + wm * 32 + mi * 16 + g;
                atomicAdd(&scOut[row], p0);
                atomicAdd(&scOut[row + 8], p1);
            }
        }
    }
}

// ---------------- GRU ----------------
__global__ void gru_kernel(const float* __restrict__ prev,
                           float* __restrict__ outHidden) {
    int idx = blockIdx.x * blockDim.x + threadIdx.x;
    int b = idx >> 9, h = idx & (H_ - 1);
    const float* gi = g_gi + (size_t)b * G_;
    const float* gh = g_gh + (size_t)b * G_;
    float ir = gi[h], iz = gi[h + H_], inn = gi[h + 2 * H_];
    float hr = gh[h], hz = gh[h + H_], hn = gh[h + 2 * H_];
    float r = 1.f / (1.f + expf(-(ir + hr)));
    float z = 1.f / (1.f + expf(-(iz + hz)));
    float n = tanhf(inn + r * hn);
    float hv = (1.f - z) * n + z * prev[idx];
    g_hidden[idx] = hv;
    outHidden[idx] = hv;
}

// ---------------- softmax (online max+sum) ----------------
__global__ void __launch_bounds__(512)
softmax_kernel(float* __restrict__ pred, const int* __restrict__ src,
               const int* __restrict__ ids) {
    __shared__ float s_lc[S_];
    __shared__ float s_m[512];
    __shared__ float s_s[512];
    __shared__ int s_cnt;
    const int b = blockIdx.x, t = threadIdx.x;
    float* row = pred + (size_t)b * V_;

    if (t == 0) s_cnt = 0;
    if (t < S_) {
        float mask = (src[b * S_ + t] == 0) ? -1000.f : 0.f;
        s_lc[t] = tanhf(g_sc[b * S_ + t] + mask);
    }
    __syncthreads();

    float m = -1e30f, s = 0.f;
    for (int v = t; v < V_; v += 512) {
        float x = row[v];
        float nm = fmaxf(m, x);
        s = s * __expf(m - nm) + __expf(x - nm);
        m = nm;
    }
    if (t < S_) {
        float x = s_lc[t];
        float nm = fmaxf(m, x);
        s = s * __expf(m - nm) + __expf(x - nm);
        m = nm;
    }
    s_m[t] = m; s_s[t] = s;
    __syncthreads();
    for (int o = 256; o; o >>= 1) {
        if (t < o) {
            float m1 = s_m[t], m2 = s_m[t + o];
            float nm = fmaxf(m1, m2);
            s_s[t] = s_s[t] * __expf(m1 - nm) + s_s[t + o] * __expf(m2 - nm);
            s_m[t] = nm;
        }
        __syncthreads();
    }
    float gmax = s_m[0];
    float inv = 1.f / s_s[0];

    for (int v = t; v < V_; v += 512) row[v] = __expf(row[v] - gmax) * inv;

    int id = ids[b];
    if (t < S_ && src[b * S_ + t] == id) atomicAdd(&s_cnt, 1);
    __syncthreads();

    if (t < S_) {
        float pc = __expf(s_lc[t] - gmax) * inv;
        atomicAdd(&row[src[b * S_ + t]], pc);
        float eq = (src[b * S_ + t] == id) ? 1.f : 0.f;
        g_attn[b * S_ + t] = pc * eq / fmaxf((float)s_cnt, 1.f);
    }
}

__global__ void __launch_bounds__(256)
weighted_kernel(const float* __restrict__ enc, float* __restrict__ outW) {
    __shared__ float s_a[S_];
    const int b = blockIdx.x, t = threadIdx.x;
    if (t < S_) s_a[t] = g_attn[b * S_ + t];
    __syncthreads();
    float4 acc = make_float4(0.f, 0.f, 0.f, 0.f);
    const float4* e4 = reinterpret_cast<const float4*>(enc + (size_t)b * S_ * (2 * H_));
    for (int s = 0; s < S_; s++) {
        float w = s_a[s];
        if (w != 0.f) {
            float4 e = e4[s * 256 + t];
            acc.x = fmaf(w, e.x, acc.x); acc.y = fmaf(w, e.y, acc.y);
            acc.z = fmaf(w, e.z, acc.z); acc.w = fmaf(w, e.w, acc.w);
        }
    }
    reinterpret_cast<float4*>(outW)[b * 256 + t] = acc;
}

// ---------------- launch ----------------
extern "C" void kernel_launch(void* const* d_in, const int* in_sizes, int n_in,
                              void* d_out, int out_size) {
    const int*   input_ids = (const int*)d_in[0];
    const float* encoded   = (const float*)d_in[1];
    const int*   src       = (const int*)d_in[2];
    const float* prev      = (const float*)d_in[3];
    const float* weighted  = (const float*)d_in[4];
    const float* embed_w   = (const float*)d_in[6];
    const float* w_ih      = (const float*)d_in[7];
    const float* w_hh      = (const float*)d_in[8];
    const float* b_ih      = (const float*)d_in[9];
    const float* b_hh      = (const float*)d_in[10];
    const float* Wo_w      = (const float*)d_in[13];
    const float* Wo_b      = (const float*)d_in[14];
    const float* Wc_w      = (const float*)d_in[15];
    const float* Wc_b      = (const float*)d_in[16];

    float* pred        = (float*)d_out;
    float* outHidden   = pred + (size_t)B_ * V_;
    float* outWeighted = outHidden + (size_t)B_ * H_;

    float *pgi, *phid, *psc;
    cudaGetSymbolAddress((void**)&pgi,  g_gi);
    cudaGetSymbolAddress((void**)&phid, g_hidden);
    cudaGetSymbolAddress((void**)&psc,  g_sc);
    __half *pph, *ppl, *pwih, *pwhh, *pwc;
    cudaGetSymbolAddress((void**)&pph,  g_prev_hi);
    cudaGetSymbolAddress((void**)&ppl,  g_prev_lo);
    cudaGetSymbolAddress((void**)&pwih, g_wih_hi);
    cudaGetSymbolAddress((void**)&pwhh, g_whh_hi);
    cudaGetSymbolAddress((void**)&pwc,  g_wc_hi);

    constexpr int SM_T = 2 * STG_A + 2 * HTILE + 3 * HTILE;       // PRE_B=true: 83968
    constexpr int SM_F = 2 * (2 * STG_A) + 3 * HTILE;             // PRE_B=false: 96256
    cudaFuncSetAttribute(mma_gemm<0, false>, cudaFuncAttributeMaxDynamicSharedMemorySize, SM_F);
    cudaFuncSetAttribute(mma_gemm<1, true>,  cudaFuncAttributeMaxDynamicSharedMemorySize, SM_T);
    cudaFuncSetAttribute(mma_gates, cudaFuncAttributeMaxDynamicSharedMemorySize, GATES_SMEM);

    // pre-splits
    build_x_split_kernel<<<(B_ * IN_) / 256, 256>>>(input_ids, embed_w, weighted);
    split_hilo_kernel<<<(B_ * H_) / 1024, 256>>>(prev, pph, ppl, B_ * H_);
    split_hi_kernel<<<(G_ * IN_) / 1024, 256>>>(w_ih, pwih, G_ * IN_);
    split_hi_kernel<<<(G_ * H_) / 1024, 256>>>(w_hh, pwhh, G_ * H_);
    split_hi_kernel<<<(H_ * 2 * H_) / 1024, 256>>>(Wc_w, pwc, H_ * 2 * H_);
    zero_kernel<<<(B_ * G_) / 256, 256>>>(pgi);
    zero_kernel<<<(B_ * S_) / 256, 256>>>(psc);

    // gates: gi (split-K=3, z=0..2) + gh (z=3) in one wave
    mma_gates<<<dim3(G_ / GN, B_ / GM, 4), 256, GATES_SMEM>>>(b_ih, b_hh);

    gru_kernel<<<(B_ * H_) / 256, 256>>>(prev, outHidden);

    // score_g = hidden @ Wo^T + Wo_b  (A,B staged fp32)
    mma_gemm<0, false><<<dim3(V_ / GN, B_ / GM), 256, SM_F>>>(
        phid, Wo_w, nullptr, Wo_b, pred, B_, V_, H_, nullptr, nullptr);

    // sc = einsum(tanh(enc @ Wc^T + Wc_b), hidden)  (B pre-split fp16)
    mma_gemm<1, true><<<dim3((2 * H_) / GN / 2, (B_ * S_) / GM), 256, SM_T>>>(
        encoded, nullptr, pwc, Wc_b, nullptr, B_ * S_, H_, 2 * H_, phid, psc);

    softmax_kernel<<<B_, 512>>>(pred, src, input_ids);
    weighted_kernel<<<B_, 256>>>(encoded, outWeighted);

    (void)in_sizes; (void)n_in; (void)out_size;
}